// round 13
// baseline (speedup 1.0000x reference)
#include <cuda_runtime.h>
#include <cuda_fp16.h>
#include <mma.h>
#include <cstdint>

using namespace nvcuda;

// Problem constants
#define CUR    1024
#define FULL   2048
#define BSZ    4
#define DMODEL 1024
#define HN     16
#define HD     64
#define PREV   (FULL - CUR)      // 1024
#define ZB     (BSZ * HN)        // 64 batched heads
#define SCALE  0.125f            // 1/sqrt(64)

// ---------------------------------------------------------------------------
// Scratch
// ---------------------------------------------------------------------------
__device__ __half g_full_h [ (size_t)FULL * BSZ * DMODEL ];
__device__ __half g_in_h   [ (size_t)CUR * BSZ * DMODEL ];
__device__ __half g_pe_h   [ (size_t)FULL * DMODEL ];
__device__ __half g_Wkv_h  [ (size_t)DMODEL * 2 * DMODEL ];
__device__ __half g_Wq_h   [ (size_t)DMODEL * DMODEL ];
__device__ __half g_Wpos_h [ (size_t)DMODEL * DMODEL ];
__device__ __half g_Wproj_h[ (size_t)DMODEL * DMODEL ];

__device__ __half g_kv [ (size_t)FULL * BSZ * 2 * HN * HD ];
__device__ __half g_qu [ (size_t)CUR * BSZ * HN * HD ];
__device__ __half g_qv [ (size_t)CUR * BSZ * HN * HD ];
__device__ __half g_r  [ (size_t)FULL * HN * HD ];
__device__ __half g_ctx[ (size_t)CUR * BSZ * HN * HD ];
__device__ __half g_scores_h[ (size_t)ZB * CUR * FULL ];
__device__ __half g_pos_h   [ (size_t)ZB * CUR * FULL ];
__device__ __half g_probs_h [ (size_t)ZB * CUR * FULL ];
__device__ float  g_beff[ DMODEL ];

#define H(x) __float2half_rn(x)

// cp.async helpers
__device__ __forceinline__ void cp16(void* smem, const void* gmem) {
    uint32_t s = (uint32_t)__cvta_generic_to_shared(smem);
    asm volatile("cp.async.cg.shared.global [%0], [%1], 16;\n" :: "r"(s), "l"(gmem));
}
#define CP_COMMIT asm volatile("cp.async.commit_group;\n" ::: "memory")
#define CP_WAIT1  asm volatile("cp.async.wait_group 1;\n" ::: "memory")
#define CP_WAIT0  asm volatile("cp.async.wait_group 0;\n" ::: "memory")

// ---------------------------------------------------------------------------
// fp32 -> fp16 convert
// ---------------------------------------------------------------------------
__global__ __launch_bounds__(256) void f2h_kernel(
    const float* __restrict__ src, __half* __restrict__ dst, int n4)
{
    int idx = blockIdx.x * 256 + threadIdx.x;
    if (idx < n4) {
        float4 v = reinterpret_cast<const float4*>(src)[idx];
        reinterpret_cast<__half2*>(dst)[idx * 2 + 0] = __floats2half2_rn(v.x, v.y);
        reinterpret_cast<__half2*>(dst)[idx * 2 + 1] = __floats2half2_rn(v.z, v.w);
    }
}

// ---------------------------------------------------------------------------
// FP16 GEMM, KC=32, cp.async double-buffered (R11 winner): C = A @ B
// 128x128 tile, 8 warps each 64x32. Static smem ~38 KB.
// ---------------------------------------------------------------------------
template<bool OUT_HALF>
__global__ __launch_bounds__(256) void gemm_hh(
    const __half* __restrict__ A, const __half* __restrict__ B,
    void* __restrict__ Cv, int M, int N, int K)
{
    __shared__ __half sA[2][128 * 40];
    __shared__ __half sB[2][32 * 136];
    __shared__ float  stg[8][256];
    int tid = threadIdx.x, warp = tid >> 5, lid = tid & 31;
    int wm = warp >> 2, wn = warp & 3;
    int m0 = blockIdx.y * 128, n0 = blockIdx.x * 128;

    wmma::fragment<wmma::accumulator, 16, 16, 16, float> acc[4][2];
#pragma unroll
    for (int i = 0; i < 4; i++)
#pragma unroll
        for (int j = 0; j < 2; j++) wmma::fill_fragment(acc[i][j], 0.f);

    int am = tid >> 1,  ak = (tid & 1) * 16;
    int bk = tid >> 3,  bn = (tid & 7) * 16;
    const __half* Abase = A + (size_t)(m0 + am) * K + ak;
    const __half* Bbase = B + (size_t)bk * N + n0 + bn;

    int KT = K >> 5;
    cp16(&sA[0][am * 40 + ak],     Abase);
    cp16(&sA[0][am * 40 + ak + 8], Abase + 8);
    cp16(&sB[0][bk * 136 + bn],     Bbase);
    cp16(&sB[0][bk * 136 + bn + 8], Bbase + 8);
    CP_COMMIT;

    for (int kt = 0; kt < KT; kt++) {
        if (kt + 1 < KT) {
            int buf = (kt + 1) & 1, k0 = (kt + 1) << 5;
            const __half* ap = Abase + k0;
            const __half* bp = Bbase + (size_t)k0 * N;
            cp16(&sA[buf][am * 40 + ak],     ap);
            cp16(&sA[buf][am * 40 + ak + 8], ap + 8);
            cp16(&sB[buf][bk * 136 + bn],     bp);
            cp16(&sB[buf][bk * 136 + bn + 8], bp + 8);
            CP_COMMIT;
            CP_WAIT1;
        } else {
            CP_WAIT0;
        }
        __syncthreads();
        int cb = kt & 1;
#pragma unroll
        for (int kk = 0; kk < 2; kk++) {
            wmma::fragment<wmma::matrix_a, 16, 16, 16, __half, wmma::row_major> af[4];
            wmma::fragment<wmma::matrix_b, 16, 16, 16, __half, wmma::row_major> bf[2];
#pragma unroll
            for (int i = 0; i < 4; i++)
                wmma::load_matrix_sync(af[i], &sA[cb][(wm * 64 + i * 16) * 40 + kk * 16], 40);
#pragma unroll
            for (int j = 0; j < 2; j++)
                wmma::load_matrix_sync(bf[j], &sB[cb][(kk * 16) * 136 + wn * 32 + j * 16], 136);
#pragma unroll
            for (int i = 0; i < 4; i++)
#pragma unroll
                for (int j = 0; j < 2; j++)
                    wmma::mma_sync(acc[i][j], af[i], bf[j], acc[i][j]);
        }
        __syncthreads();
    }

    if (OUT_HALF) {
        __half* C = reinterpret_cast<__half*>(Cv);
        int rr = lid >> 1, cc = (lid & 1) * 8;
#pragma unroll
        for (int i = 0; i < 4; i++)
#pragma unroll
            for (int j = 0; j < 2; j++) {
                wmma::store_matrix_sync(&stg[warp][0], acc[i][j], 16, wmma::mem_row_major);
                __syncwarp();
                const float* src = &stg[warp][rr * 16 + cc];
                __half* dst = C + (size_t)(m0 + wm * 64 + i * 16 + rr) * N
                                + n0 + wn * 32 + j * 16 + cc;
#pragma unroll
                for (int t = 0; t < 8; t += 2)
                    *reinterpret_cast<__half2*>(dst + t) = __floats2half2_rn(src[t], src[t + 1]);
                __syncwarp();
            }
    } else {
        float* C = reinterpret_cast<float*>(Cv);
#pragma unroll
        for (int i = 0; i < 4; i++)
#pragma unroll
            for (int j = 0; j < 2; j++)
                wmma::store_matrix_sync(
                    C + (size_t)(m0 + wm * 64 + i * 16) * N + n0 + wn * 32 + j * 16,
                    acc[i][j], N, wmma::mem_row_major);
    }
}

// ---------------------------------------------------------------------------
// q-projection GEMM (same KC=32 mainloop) with fused qu/qv epilogue:
//   qu = A@B + (b_q + u)[n], qv = A@B + (b_q + v)[n], fp16 outputs. N=K=1024.
// ---------------------------------------------------------------------------
__global__ __launch_bounds__(256) void gemm_quv(
    const __half* __restrict__ A, const __half* __restrict__ B,
    const float* __restrict__ b_q, const float* __restrict__ u,
    const float* __restrict__ v,
    __half* __restrict__ qu, __half* __restrict__ qv)
{
    const int N = DMODEL, K = DMODEL;
    __shared__ __half sA[2][128 * 40];
    __shared__ __half sB[2][32 * 136];
    __shared__ float  stg[8][256];
    int tid = threadIdx.x, warp = tid >> 5, lid = tid & 31;
    int wm = warp >> 2, wn = warp & 3;
    int m0 = blockIdx.y * 128, n0 = blockIdx.x * 128;

    wmma::fragment<wmma::accumulator, 16, 16, 16, float> acc[4][2];
#pragma unroll
    for (int i = 0; i < 4; i++)
#pragma unroll
        for (int j = 0; j < 2; j++) wmma::fill_fragment(acc[i][j], 0.f);

    int am = tid >> 1,  ak = (tid & 1) * 16;
    int bk = tid >> 3,  bn = (tid & 7) * 16;
    const __half* Abase = A + (size_t)(m0 + am) * K + ak;
    const __half* Bbase = B + (size_t)bk * N + n0 + bn;

    int KT = K >> 5;
    cp16(&sA[0][am * 40 + ak],     Abase);
    cp16(&sA[0][am * 40 + ak + 8], Abase + 8);
    cp16(&sB[0][bk * 136 + bn],     Bbase);
    cp16(&sB[0][bk * 136 + bn + 8], Bbase + 8);
    CP_COMMIT;

    for (int kt = 0; kt < KT; kt++) {
        if (kt + 1 < KT) {
            int buf = (kt + 1) & 1, k0 = (kt + 1) << 5;
            const __half* ap = Abase + k0;
            const __half* bp = Bbase + (size_t)k0 * N;
            cp16(&sA[buf][am * 40 + ak],     ap);
            cp16(&sA[buf][am * 40 + ak + 8], ap + 8);
            cp16(&sB[buf][bk * 136 + bn],     bp);
            cp16(&sB[buf][bk * 136 + bn + 8], bp + 8);
            CP_COMMIT;
            CP_WAIT1;
        } else {
            CP_WAIT0;
        }
        __syncthreads();
        int cb = kt & 1;
#pragma unroll
        for (int kk = 0; kk < 2; kk++) {
            wmma::fragment<wmma::matrix_a, 16, 16, 16, __half, wmma::row_major> af[4];
            wmma::fragment<wmma::matrix_b, 16, 16, 16, __half, wmma::row_major> bf[2];
#pragma unroll
            for (int i = 0; i < 4; i++)
                wmma::load_matrix_sync(af[i], &sA[cb][(wm * 64 + i * 16) * 40 + kk * 16], 40);
#pragma unroll
            for (int j = 0; j < 2; j++)
                wmma::load_matrix_sync(bf[j], &sB[cb][(kk * 16) * 136 + wn * 32 + j * 16], 136);
#pragma unroll
            for (int i = 0; i < 4; i++)
#pragma unroll
                for (int j = 0; j < 2; j++)
                    wmma::mma_sync(acc[i][j], af[i], bf[j], acc[i][j]);
        }
        __syncthreads();
    }

    int rr = lid >> 1, cc = (lid & 1) * 8;
#pragma unroll
    for (int i = 0; i < 4; i++)
#pragma unroll
        for (int j = 0; j < 2; j++) {
            wmma::store_matrix_sync(&stg[warp][0], acc[i][j], 16, wmma::mem_row_major);
            __syncwarp();
            const float* src = &stg[warp][rr * 16 + cc];
            size_t row = (size_t)(m0 + wm * 64 + i * 16 + rr) * N;
            int n = n0 + wn * 32 + j * 16 + cc;
#pragma unroll
            for (int t = 0; t < 8; t += 2) {
                float a0 = src[t]     + b_q[n + t];
                float a1 = src[t + 1] + b_q[n + t + 1];
                *reinterpret_cast<__half2*>(qu + row + n + t) =
                    __floats2half2_rn(a0 + u[n + t], a1 + u[n + t + 1]);
                *reinterpret_cast<__half2*>(qv + row + n + t) =
                    __floats2half2_rn(a0 + v[n + t], a1 + v[n + t + 1]);
            }
            __syncwarp();
        }
}

// ---------------------------------------------------------------------------
__global__ __launch_bounds__(256) void beff_kernel(
    const float* __restrict__ b_kv, const float* __restrict__ W_proj,
    const float* __restrict__ b_proj, float* __restrict__ beff)
{
    int n = blockIdx.x * 256 + threadIdx.x;
    float acc = b_proj[n];
    for (int m = 0; m < DMODEL; m++)
        acc += b_kv[DMODEL + m] * W_proj[(size_t)m * DMODEL + n];
    beff[n] = acc;
}

__global__ __launch_bounds__(256) void bias_add_kernel(
    float* __restrict__ out, const float* __restrict__ beff)
{
    int idx = blockIdx.x * 256 + threadIdx.x;
    int n4 = idx & 255;
    float4 o = reinterpret_cast<float4*>(out)[idx];
    float4 b = reinterpret_cast<const float4*>(beff)[n4];
    o.x += b.x; o.y += b.y; o.z += b.z; o.w += b.w;
    reinterpret_cast<float4*>(out)[idx] = o;
}

// ---------------------------------------------------------------------------
// Score GEMM (fp16 in/out), single-shot K=64.  (unchanged R11)
// ---------------------------------------------------------------------------
#define SCORE_SMEM_BYTES (128 * 132 * 4)
__global__ __launch_bounds__(256) void score_h(
    const __half* __restrict__ QU, const __half* __restrict__ SRC,
    __half* __restrict__ OUT, int isPos)
{
    int i0 = blockIdx.y * 128, j0 = blockIdx.x * 128;
    if (!isPos && j0 >= i0 + 1152) return;
    if (isPos && (i0 + j0 + 254) < 1023) return;
    int z = blockIdx.z;
    int b = z >> 4, h = z & 15;
    const __half* A0 = QU + b * DMODEL + h * HD;
    const __half* B0 = isPos ? (SRC + h * HD) : (SRC + b * 2048 + h * HD);
    size_t ldB = isPos ? (size_t)(HN * HD) : (size_t)(BSZ * 2 * HN * HD);

    extern __shared__ char dynsm[];
    __half* sA = reinterpret_cast<__half*>(dynsm);           // 128 x 72
    __half* sB = sA + 128 * 72;
    float*  stage = reinterpret_cast<float*>(dynsm);

    int tid = threadIdx.x, warp = tid >> 5;
    int wm = warp >> 2, wn = warp & 3;

    wmma::fragment<wmma::accumulator, 16, 16, 16, float> acc[4][2];
#pragma unroll
    for (int i = 0; i < 4; i++)
#pragma unroll
        for (int j = 0; j < 2; j++) wmma::fill_fragment(acc[i][j], 0.f);

    int rm = tid >> 1, rk = (tid & 1) * 32;
    {
        const __half* ap = A0 + (size_t)(i0 + rm) * (BSZ * DMODEL) + rk;
        __half* sa = sA + rm * 72 + rk;
#pragma unroll
        for (int s = 0; s < 4; s++)
            *reinterpret_cast<uint4*>(sa + 8 * s) = *reinterpret_cast<const uint4*>(ap + 8 * s);
        const __half* bp = B0 + (size_t)(j0 + rm) * ldB + rk;
        __half* sb = sB + rm * 72 + rk;
#pragma unroll
        for (int s = 0; s < 4; s++)
            *reinterpret_cast<uint4*>(sb + 8 * s) = *reinterpret_cast<const uint4*>(bp + 8 * s);
    }
    __syncthreads();
#pragma unroll
    for (int kk = 0; kk < 4; kk++) {
        wmma::fragment<wmma::matrix_a, 16, 16, 16, __half, wmma::row_major> af[4];
        wmma::fragment<wmma::matrix_b, 16, 16, 16, __half, wmma::col_major> bf[2];
#pragma unroll
        for (int i = 0; i < 4; i++)
            wmma::load_matrix_sync(af[i], &sA[(wm * 64 + i * 16) * 72 + kk * 16], 72);
#pragma unroll
        for (int j = 0; j < 2; j++)
            wmma::load_matrix_sync(bf[j], &sB[(wn * 32 + j * 16) * 72 + kk * 16], 72);
#pragma unroll
        for (int i = 0; i < 4; i++)
#pragma unroll
            for (int j = 0; j < 2; j++)
                wmma::mma_sync(acc[i][j], af[i], bf[j], acc[i][j]);
    }
    __syncthreads();

#pragma unroll
    for (int i = 0; i < 4; i++)
#pragma unroll
        for (int j = 0; j < 2; j++)
            wmma::store_matrix_sync(&stage[(wm * 64 + i * 16) * 132 + wn * 32 + j * 16],
                                    acc[i][j], 132, wmma::mem_row_major);
    __syncthreads();

    __half* C0 = OUT + (size_t)z * CUR * FULL;
    int row = tid >> 1, cb = (tid & 1) * 64;
    __half* dst = C0 + (size_t)(i0 + row) * FULL + j0 + cb;
    const float* src = stage + row * 132 + cb;
#pragma unroll
    for (int t = 0; t < 64; t += 2)
        *reinterpret_cast<__half2*>(dst + t) = __floats2half2_rn(src[t], src[t + 1]);
}

// ---------------------------------------------------------------------------
// Fused rel_shift gather + mask + softmax; writes only columns the ctx GEMM
// reads: [0, (i & ~127) + 1152).
// ---------------------------------------------------------------------------
__global__ __launch_bounds__(256) void softmax_kernel(
    const __half* __restrict__ cont, const __half* __restrict__ pos,
    __half* __restrict__ out)
{
    int i = blockIdx.x;
    int z = blockIdx.y;
    int tid = threadIdx.x;
    size_t rowOff = ((size_t)z * CUR + i) * FULL;
    const __half* c = cont + rowOff;
    const __half* p = pos + rowOff;
    int jmax  = i + PREV;
    int shift = CUR - 1 - i;
    int WR = (i & ~127) + 1152;  if (WR > FULL) WR = FULL;

    float vals[8];
    float mx = -1e30f;
#pragma unroll
    for (int it = 0; it < 8; it++) {
        int j = tid + it * 256;
        float s = -1e30f;
        if (j <= jmax)
            s = (__half2float(c[j]) + __half2float(p[j + shift])) * SCALE;
        vals[it] = s;
        mx = fmaxf(mx, s);
    }
    __shared__ float redm[8];
    __shared__ float reds[8];
#pragma unroll
    for (int o = 16; o; o >>= 1) mx = fmaxf(mx, __shfl_xor_sync(0xffffffffu, mx, o));
    if ((tid & 31) == 0) redm[tid >> 5] = mx;
    __syncthreads();
    mx = redm[0];
#pragma unroll
    for (int w = 1; w < 8; w++) mx = fmaxf(mx, redm[w]);

    float sum = 0.f;
#pragma unroll
    for (int it = 0; it < 8; it++) {
        float e = __expf(vals[it] - mx);
        vals[it] = e;
        sum += e;
    }
#pragma unroll
    for (int o = 16; o; o >>= 1) sum += __shfl_xor_sync(0xffffffffu, sum, o);
    if ((tid & 31) == 0) reds[tid >> 5] = sum;
    __syncthreads();
    sum = 0.f;
#pragma unroll
    for (int w = 0; w < 8; w++) sum += reds[w];
    float inv = 1.f / sum;

    __half* o = out + rowOff;
#pragma unroll
    for (int it = 0; it < 8; it++) {
        int j = tid + it * 256;
        if (j < WR)
            o[j] = (j <= jmax) ? H(vals[it] * inv) : __half(0.f);
    }
}

// ---------------------------------------------------------------------------
// Context GEMM fp16, cp.async double-buffered. K truncated at i0+1152. (R11)
// ---------------------------------------------------------------------------
__global__ __launch_bounds__(256) void ctx_h(
    const __half* __restrict__ probs, const __half* __restrict__ kv,
    __half* __restrict__ ctx)
{
    int z = blockIdx.y;
    int b = z >> 4, h = z & 15;
    int i0 = blockIdx.x * 128;
    const __half* A0 = probs + (size_t)z * CUR * FULL;
    const __half* B0 = kv + (size_t)b * 2048 + DMODEL + h * HD;

    __shared__ __half sA[2][128 * 40];
    __shared__ __half sB[2][32 * 72];
    __shared__ float  stg[8][256];
    int tid = threadIdx.x, warp = tid >> 5, lid = tid & 31;
    int wm = warp >> 1, wn = warp & 1;

    wmma::fragment<wmma::accumulator, 16, 16, 16, float> acc[2][2];
#pragma unroll
    for (int i = 0; i < 2; i++)
#pragma unroll
        for (int j = 0; j < 2; j++) wmma::fill_fragment(acc[i][j], 0.f);

    int am = tid >> 1, aj = (tid & 1) * 16;
    int bj = tid >> 3, bd = (tid & 7) * 8;
    const __half* Abase = A0 + (size_t)(i0 + am) * FULL + aj;
    const __half* Bbase = B0 + (size_t)bj * (BSZ * 2 * HN * HD) + bd;
    const size_t bstr = (size_t)(BSZ * 2 * HN * HD);

    int kmax = i0 + 1152;  if (kmax > FULL) kmax = FULL;
    int KT = kmax >> 5;

    cp16(&sA[0][am * 40 + aj],     Abase);
    cp16(&sA[0][am * 40 + aj + 8], Abase + 8);
    cp16(&sB[0][bj * 72 + bd],     Bbase);
    CP_COMMIT;

    for (int kt = 0; kt < KT; kt++) {
        if (kt + 1 < KT) {
            int buf = (kt + 1) & 1, k0 = (kt + 1) << 5;
            const __half* ap = Abase + k0;
            const __half* bp = Bbase + (size_t)k0 * bstr;
            cp16(&sA[buf][am * 40 + aj],     ap);
            cp16(&sA[buf][am * 40 + aj + 8], ap + 8);
            cp16(&sB[buf][bj * 72 + bd],     bp);
            CP_COMMIT;
            CP_WAIT1;
        } else {
            CP_WAIT0;
        }
        __syncthreads();
        int cb = kt & 1;
#pragma unroll
        for (int kk = 0; kk < 2; kk++) {
            wmma::fragment<wmma::matrix_a, 16, 16, 16, __half, wmma::row_major> af[2];
            wmma::fragment<wmma::matrix_b, 16, 16, 16, __half, wmma::row_major> bf[2];
#pragma unroll
            for (int i = 0; i < 2; i++)
                wmma::load_matrix_sync(af[i], &sA[cb][(wm * 32 + i * 16) * 40 + kk * 16], 40);
#pragma unroll
            for (int j = 0; j < 2; j++)
                wmma::load_matrix_sync(bf[j], &sB[cb][(kk * 16) * 72 + wn * 32 + j * 16], 72);
#pragma unroll
            for (int i = 0; i < 2; i++)
#pragma unroll
                for (int j = 0; j < 2; j++)
                    wmma::mma_sync(acc[i][j], af[i], bf[j], acc[i][j]);
        }
        __syncthreads();
    }
    int rr = lid >> 1, cc = (lid & 1) * 8;
#pragma unroll
    for (int i = 0; i < 2; i++)
#pragma unroll
        for (int j = 0; j < 2; j++) {
            wmma::store_matrix_sync(&stg[warp][0], acc[i][j], 16, wmma::mem_row_major);
            __syncwarp();
            const float* src = &stg[warp][rr * 16 + cc];
            __half* dst = ctx + (size_t)((i0 + wm * 32 + i * 16 + rr) * BSZ + b) * DMODEL
                              + h * HD + wn * 32 + j * 16 + cc;
#pragma unroll
            for (int t = 0; t < 8; t += 2)
                *reinterpret_cast<__half2*>(dst + t) = __floats2half2_rn(src[t], src[t + 1]);
            __syncwarp();
        }
}

// ---------------------------------------------------------------------------
// Launch
// ---------------------------------------------------------------------------
extern "C" void kernel_launch(void* const* d_in, const int* in_sizes, int n_in,
                              void* d_out, int out_size)
{
    const float* inputs  = (const float*)d_in[0];
    const float* pos_emb = (const float*)d_in[1];
    const float* full_in = (const float*)d_in[2];
    const float* u       = (const float*)d_in[3];
    const float* v       = (const float*)d_in[4];
    const float* W_kv    = (const float*)d_in[6];
    const float* b_kv    = (const float*)d_in[7];
    const float* W_q     = (const float*)d_in[8];
    const float* b_q     = (const float*)d_in[9];
    const float* W_pos   = (const float*)d_in[10];
    const float* W_proj  = (const float*)d_in[12];
    const float* b_proj  = (const float*)d_in[13];
    float* out = (float*)d_out;

    float *beff;
    __half *fullh, *inh, *peh, *Wkvh, *Wqh, *Wposh, *Wprojh;
    __half *kv, *qu, *qv, *r, *ctx, *scores, *pos, *probs;
    cudaGetSymbolAddress((void**)&fullh,  g_full_h);
    cudaGetSymbolAddress((void**)&inh,    g_in_h);
    cudaGetSymbolAddress((void**)&peh,    g_pe_h);
    cudaGetSymbolAddress((void**)&Wkvh,   g_Wkv_h);
    cudaGetSymbolAddress((void**)&Wqh,    g_Wq_h);
    cudaGetSymbolAddress((void**)&Wposh,  g_Wpos_h);
    cudaGetSymbolAddress((void**)&Wprojh, g_Wproj_h);
    cudaGetSymbolAddress((void**)&kv,     g_kv);
    cudaGetSymbolAddress((void**)&qu,     g_qu);
    cudaGetSymbolAddress((void**)&qv,     g_qv);
    cudaGetSymbolAddress((void**)&r,      g_r);
    cudaGetSymbolAddress((void**)&ctx,    g_ctx);
    cudaGetSymbolAddress((void**)&scores, g_scores_h);
    cudaGetSymbolAddress((void**)&pos,    g_pos_h);
    cudaGetSymbolAddress((void**)&probs,  g_probs_h);
    cudaGetSymbolAddress((void**)&beff,   g_beff);

    static int attr_set = 0;
    if (!attr_set) {
        cudaFuncSetAttribute(score_h, cudaFuncAttributeMaxDynamicSharedMemorySize,
                             SCORE_SMEM_BYTES);
        attr_set = 1;
    }

    // fp32 -> fp16 converts
    f2h_kernel<<<(8192 * 1024 / 4) / 256, 256>>>(full_in, fullh, 8192 * 1024 / 4);
    f2h_kernel<<<(4096 * 1024 / 4) / 256, 256>>>(inputs, inh, 4096 * 1024 / 4);
    f2h_kernel<<<(2048 * 1024 / 4) / 256, 256>>>(pos_emb, peh, 2048 * 1024 / 4);
    f2h_kernel<<<(1024 * 2048 / 4) / 256, 256>>>(W_kv, Wkvh, 1024 * 2048 / 4);
    f2h_kernel<<<(1024 * 1024 / 4) / 256, 256>>>(W_q, Wqh, 1024 * 1024 / 4);
    f2h_kernel<<<(1024 * 1024 / 4) / 256, 256>>>(W_pos, Wposh, 1024 * 1024 / 4);
    f2h_kernel<<<(1024 * 1024 / 4) / 256, 256>>>(W_proj, Wprojh, 1024 * 1024 / 4);

    // Projections (KC=32 pipelined; q-proj fuses qu/qv epilogue)
    gemm_hh<true ><<<dim3(2048 / 128, 8192 / 128), 256>>>(fullh, Wkvh, kv, 8192, 2048, 1024);
    gemm_quv<<<dim3(1024 / 128, 4096 / 128), 256>>>(inh, Wqh, b_q, u, v, qu, qv);
    gemm_hh<true ><<<dim3(1024 / 128, 2048 / 128), 256>>>(peh, Wposh, r, 2048, 1024, 1024);

    beff_kernel<<<DMODEL / 256, 256>>>(b_kv, W_proj, b_proj, beff);

    // Scores (fp16 in/out)
    score_h<<<dim3(FULL / 128, CUR / 128, ZB), 256, SCORE_SMEM_BYTES>>>(qu, kv, scores, 0);
    score_h<<<dim3(FULL / 128, CUR / 128, ZB), 256, SCORE_SMEM_BYTES>>>(qv, r, pos, 1);

    // shift + mask + softmax -> fp16 probs (write-trimmed)
    softmax_kernel<<<dim3(CUR, ZB), 256>>>(scores, pos, probs);

    // ctx = probs @ val
    ctx_h<<<dim3(CUR / 128, ZB), 256>>>(probs, kv, ctx);

    // out = ctx @ W_proj + b_eff
    gemm_hh<false><<<dim3(1024 / 128, 4096 / 128), 256>>>(ctx, Wprojh, out, 4096, 1024, 1024);
    bias_add_kernel<<<4096, 256>>>(out, beff);

    (void)in_sizes; (void)n_in; (void)out_size;
}

// round 14
// speedup vs baseline: 1.4787x; 1.4787x over previous
#include <cuda_runtime.h>
#include <cuda_fp16.h>
#include <mma.h>
#include <cstdint>

using namespace nvcuda;

// Problem constants
#define CUR    1024
#define FULL   2048
#define BSZ    4
#define DMODEL 1024
#define HN     16
#define HD     64
#define PREV   (FULL - CUR)      // 1024
#define ZB     (BSZ * HN)        // 64 batched heads
#define SCALE  0.125f            // 1/sqrt(64)

// ---------------------------------------------------------------------------
// Scratch
// ---------------------------------------------------------------------------
__device__ __half g_full_h [ (size_t)FULL * BSZ * DMODEL ];
__device__ __half g_in_h   [ (size_t)CUR * BSZ * DMODEL ];
__device__ __half g_pe_h   [ (size_t)FULL * DMODEL ];
__device__ __half g_Wkv_h  [ (size_t)DMODEL * 2 * DMODEL ];
__device__ __half g_Wq_h   [ (size_t)DMODEL * DMODEL ];
__device__ __half g_Wpos_h [ (size_t)DMODEL * DMODEL ];
__device__ __half g_Wproj_h[ (size_t)DMODEL * DMODEL ];

__device__ __half g_kv [ (size_t)FULL * BSZ * 2 * HN * HD ];
__device__ float  g_q  [ (size_t)CUR * BSZ * HN * HD ];
__device__ __half g_qu [ (size_t)CUR * BSZ * HN * HD ];
__device__ __half g_qv [ (size_t)CUR * BSZ * HN * HD ];
__device__ __half g_r  [ (size_t)FULL * HN * HD ];
__device__ __half g_ctx[ (size_t)CUR * BSZ * HN * HD ];
__device__ __half g_scores_h[ (size_t)ZB * CUR * FULL ];
__device__ __half g_pos_h   [ (size_t)ZB * CUR * FULL ];
__device__ __half g_probs_h [ (size_t)ZB * CUR * FULL ];
__device__ float  g_beff[ DMODEL ];

#define H(x) __float2half_rn(x)

// cp.async helpers
__device__ __forceinline__ void cp16(void* smem, const void* gmem) {
    uint32_t s = (uint32_t)__cvta_generic_to_shared(smem);
    asm volatile("cp.async.cg.shared.global [%0], [%1], 16;\n" :: "r"(s), "l"(gmem));
}
#define CP_COMMIT asm volatile("cp.async.commit_group;\n" ::: "memory")
#define CP_WAIT1  asm volatile("cp.async.wait_group 1;\n" ::: "memory")
#define CP_WAIT0  asm volatile("cp.async.wait_group 0;\n" ::: "memory")

// ---------------------------------------------------------------------------
// fp32 -> fp16 convert
// ---------------------------------------------------------------------------
__global__ __launch_bounds__(256) void f2h_kernel(
    const float* __restrict__ src, __half* __restrict__ dst, int n4)
{
    int idx = blockIdx.x * 256 + threadIdx.x;
    if (idx < n4) {
        float4 v = reinterpret_cast<const float4*>(src)[idx];
        reinterpret_cast<__half2*>(dst)[idx * 2 + 0] = __floats2half2_rn(v.x, v.y);
        reinterpret_cast<__half2*>(dst)[idx * 2 + 1] = __floats2half2_rn(v.z, v.w);
    }
}

// ---------------------------------------------------------------------------
// FP16 GEMM, KC=32, cp.async double-buffered (R11 winner): C = A @ B
// 128x128 tile, 8 warps each 64x32. Static smem ~45 KB.
// ---------------------------------------------------------------------------
template<bool OUT_HALF>
__global__ __launch_bounds__(256) void gemm_hh(
    const __half* __restrict__ A, const __half* __restrict__ B,
    void* __restrict__ Cv, int M, int N, int K)
{
    __shared__ __half sA[2][128 * 40];
    __shared__ __half sB[2][32 * 136];
    __shared__ float  stg[8][256];
    int tid = threadIdx.x, warp = tid >> 5, lid = tid & 31;
    int wm = warp >> 2, wn = warp & 3;
    int m0 = blockIdx.y * 128, n0 = blockIdx.x * 128;

    wmma::fragment<wmma::accumulator, 16, 16, 16, float> acc[4][2];
#pragma unroll
    for (int i = 0; i < 4; i++)
#pragma unroll
        for (int j = 0; j < 2; j++) wmma::fill_fragment(acc[i][j], 0.f);

    int am = tid >> 1,  ak = (tid & 1) * 16;
    int bk = tid >> 3,  bn = (tid & 7) * 16;
    const __half* Abase = A + (size_t)(m0 + am) * K + ak;
    const __half* Bbase = B + (size_t)bk * N + n0 + bn;

    int KT = K >> 5;
    cp16(&sA[0][am * 40 + ak],     Abase);
    cp16(&sA[0][am * 40 + ak + 8], Abase + 8);
    cp16(&sB[0][bk * 136 + bn],     Bbase);
    cp16(&sB[0][bk * 136 + bn + 8], Bbase + 8);
    CP_COMMIT;

    for (int kt = 0; kt < KT; kt++) {
        if (kt + 1 < KT) {
            int buf = (kt + 1) & 1, k0 = (kt + 1) << 5;
            const __half* ap = Abase + k0;
            const __half* bp = Bbase + (size_t)k0 * N;
            cp16(&sA[buf][am * 40 + ak],     ap);
            cp16(&sA[buf][am * 40 + ak + 8], ap + 8);
            cp16(&sB[buf][bk * 136 + bn],     bp);
            cp16(&sB[buf][bk * 136 + bn + 8], bp + 8);
            CP_COMMIT;
            CP_WAIT1;
        } else {
            CP_WAIT0;
        }
        __syncthreads();
        int cb = kt & 1;
#pragma unroll
        for (int kk = 0; kk < 2; kk++) {
            wmma::fragment<wmma::matrix_a, 16, 16, 16, __half, wmma::row_major> af[4];
            wmma::fragment<wmma::matrix_b, 16, 16, 16, __half, wmma::row_major> bf[2];
#pragma unroll
            for (int i = 0; i < 4; i++)
                wmma::load_matrix_sync(af[i], &sA[cb][(wm * 64 + i * 16) * 40 + kk * 16], 40);
#pragma unroll
            for (int j = 0; j < 2; j++)
                wmma::load_matrix_sync(bf[j], &sB[cb][(kk * 16) * 136 + wn * 32 + j * 16], 136);
#pragma unroll
            for (int i = 0; i < 4; i++)
#pragma unroll
                for (int j = 0; j < 2; j++)
                    wmma::mma_sync(acc[i][j], af[i], bf[j], acc[i][j]);
        }
        __syncthreads();
    }

    if (OUT_HALF) {
        __half* C = reinterpret_cast<__half*>(Cv);
        int rr = lid >> 1, cc = (lid & 1) * 8;
#pragma unroll
        for (int i = 0; i < 4; i++)
#pragma unroll
            for (int j = 0; j < 2; j++) {
                wmma::store_matrix_sync(&stg[warp][0], acc[i][j], 16, wmma::mem_row_major);
                __syncwarp();
                const float* src = &stg[warp][rr * 16 + cc];
                __half* dst = C + (size_t)(m0 + wm * 64 + i * 16 + rr) * N
                                + n0 + wn * 32 + j * 16 + cc;
#pragma unroll
                for (int t = 0; t < 8; t += 2)
                    *reinterpret_cast<__half2*>(dst + t) = __floats2half2_rn(src[t], src[t + 1]);
                __syncwarp();
            }
    } else {
        float* C = reinterpret_cast<float*>(Cv);
#pragma unroll
        for (int i = 0; i < 4; i++)
#pragma unroll
            for (int j = 0; j < 2; j++)
                wmma::store_matrix_sync(
                    C + (size_t)(m0 + wm * 64 + i * 16) * N + n0 + wn * 32 + j * 16,
                    acc[i][j], N, wmma::mem_row_major);
    }
}

// ---------------------------------------------------------------------------
// qu/qv, beff, bias add (R11 versions)
// ---------------------------------------------------------------------------
__global__ __launch_bounds__(256) void quv_kernel(
    const float* __restrict__ q, const float* __restrict__ b_q,
    const float* __restrict__ u, const float* __restrict__ v,
    __half* __restrict__ qu, __half* __restrict__ qv)
{
    int idx = blockIdx.x * 256 + threadIdx.x;
    int n4 = idx & 255;
    float4 qq = reinterpret_cast<const float4*>(q)[idx];
    float4 bb = reinterpret_cast<const float4*>(b_q)[n4];
    float4 uu = reinterpret_cast<const float4*>(u)[n4];
    float4 vv = reinterpret_cast<const float4*>(v)[n4];
    reinterpret_cast<__half2*>(qu)[idx * 2 + 0] = __floats2half2_rn(qq.x + bb.x + uu.x, qq.y + bb.y + uu.y);
    reinterpret_cast<__half2*>(qu)[idx * 2 + 1] = __floats2half2_rn(qq.z + bb.z + uu.z, qq.w + bb.w + uu.w);
    reinterpret_cast<__half2*>(qv)[idx * 2 + 0] = __floats2half2_rn(qq.x + bb.x + vv.x, qq.y + bb.y + vv.y);
    reinterpret_cast<__half2*>(qv)[idx * 2 + 1] = __floats2half2_rn(qq.z + bb.z + vv.z, qq.w + bb.w + vv.w);
}

__global__ __launch_bounds__(256) void beff_kernel(
    const float* __restrict__ b_kv, const float* __restrict__ W_proj,
    const float* __restrict__ b_proj, float* __restrict__ beff)
{
    int n = blockIdx.x * 256 + threadIdx.x;
    float acc = b_proj[n];
    for (int m = 0; m < DMODEL; m++)
        acc += b_kv[DMODEL + m] * W_proj[(size_t)m * DMODEL + n];
    beff[n] = acc;
}

__global__ __launch_bounds__(256) void bias_add_kernel(
    float* __restrict__ out, const float* __restrict__ beff)
{
    int idx = blockIdx.x * 256 + threadIdx.x;
    int n4 = idx & 255;
    float4 o = reinterpret_cast<float4*>(out)[idx];
    float4 b = reinterpret_cast<const float4*>(beff)[n4];
    o.x += b.x; o.y += b.y; o.z += b.z; o.w += b.w;
    reinterpret_cast<float4*>(out)[idx] = o;
}

// ---------------------------------------------------------------------------
// Score GEMM (fp16 in/out), single-shot K=64.  (R11)
// ---------------------------------------------------------------------------
#define SCORE_SMEM_BYTES (128 * 132 * 4)
__global__ __launch_bounds__(256) void score_h(
    const __half* __restrict__ QU, const __half* __restrict__ SRC,
    __half* __restrict__ OUT, int isPos)
{
    int i0 = blockIdx.y * 128, j0 = blockIdx.x * 128;
    if (!isPos && j0 >= i0 + 1152) return;
    if (isPos && (i0 + j0 + 254) < 1023) return;
    int z = blockIdx.z;
    int b = z >> 4, h = z & 15;
    const __half* A0 = QU + b * DMODEL + h * HD;
    const __half* B0 = isPos ? (SRC + h * HD) : (SRC + b * 2048 + h * HD);
    size_t ldB = isPos ? (size_t)(HN * HD) : (size_t)(BSZ * 2 * HN * HD);

    extern __shared__ char dynsm[];
    __half* sA = reinterpret_cast<__half*>(dynsm);           // 128 x 72
    __half* sB = sA + 128 * 72;
    float*  stage = reinterpret_cast<float*>(dynsm);

    int tid = threadIdx.x, warp = tid >> 5;
    int wm = warp >> 2, wn = warp & 3;

    wmma::fragment<wmma::accumulator, 16, 16, 16, float> acc[4][2];
#pragma unroll
    for (int i = 0; i < 4; i++)
#pragma unroll
        for (int j = 0; j < 2; j++) wmma::fill_fragment(acc[i][j], 0.f);

    int rm = tid >> 1, rk = (tid & 1) * 32;
    {
        const __half* ap = A0 + (size_t)(i0 + rm) * (BSZ * DMODEL) + rk;
        __half* sa = sA + rm * 72 + rk;
#pragma unroll
        for (int s = 0; s < 4; s++)
            *reinterpret_cast<uint4*>(sa + 8 * s) = *reinterpret_cast<const uint4*>(ap + 8 * s);
        const __half* bp = B0 + (size_t)(j0 + rm) * ldB + rk;
        __half* sb = sB + rm * 72 + rk;
#pragma unroll
        for (int s = 0; s < 4; s++)
            *reinterpret_cast<uint4*>(sb + 8 * s) = *reinterpret_cast<const uint4*>(bp + 8 * s);
    }
    __syncthreads();
#pragma unroll
    for (int kk = 0; kk < 4; kk++) {
        wmma::fragment<wmma::matrix_a, 16, 16, 16, __half, wmma::row_major> af[4];
        wmma::fragment<wmma::matrix_b, 16, 16, 16, __half, wmma::col_major> bf[2];
#pragma unroll
        for (int i = 0; i < 4; i++)
            wmma::load_matrix_sync(af[i], &sA[(wm * 64 + i * 16) * 72 + kk * 16], 72);
#pragma unroll
        for (int j = 0; j < 2; j++)
            wmma::load_matrix_sync(bf[j], &sB[(wn * 32 + j * 16) * 72 + kk * 16], 72);
#pragma unroll
        for (int i = 0; i < 4; i++)
#pragma unroll
            for (int j = 0; j < 2; j++)
                wmma::mma_sync(acc[i][j], af[i], bf[j], acc[i][j]);
    }
    __syncthreads();

#pragma unroll
    for (int i = 0; i < 4; i++)
#pragma unroll
        for (int j = 0; j < 2; j++)
            wmma::store_matrix_sync(&stage[(wm * 64 + i * 16) * 132 + wn * 32 + j * 16],
                                    acc[i][j], 132, wmma::mem_row_major);
    __syncthreads();

    __half* C0 = OUT + (size_t)z * CUR * FULL;
    int row = tid >> 1, cb = (tid & 1) * 64;
    __half* dst = C0 + (size_t)(i0 + row) * FULL + j0 + cb;
    const float* src = stage + row * 132 + cb;
#pragma unroll
    for (int t = 0; t < 64; t += 2)
        *reinterpret_cast<__half2*>(dst + t) = __floats2half2_rn(src[t], src[t + 1]);
}

// ---------------------------------------------------------------------------
// Fused rel_shift gather + mask + softmax; writes only columns the ctx GEMM
// reads: [0, (i & ~127) + 1152).  (only change vs R11)
// ---------------------------------------------------------------------------
__global__ __launch_bounds__(256) void softmax_kernel(
    const __half* __restrict__ cont, const __half* __restrict__ pos,
    __half* __restrict__ out)
{
    int i = blockIdx.x;
    int z = blockIdx.y;
    int tid = threadIdx.x;
    size_t rowOff = ((size_t)z * CUR + i) * FULL;
    const __half* c = cont + rowOff;
    const __half* p = pos + rowOff;
    int jmax  = i + PREV;
    int shift = CUR - 1 - i;
    int WR = (i & ~127) + 1152;  if (WR > FULL) WR = FULL;

    float vals[8];
    float mx = -1e30f;
#pragma unroll
    for (int it = 0; it < 8; it++) {
        int j = tid + it * 256;
        float s = -1e30f;
        if (j <= jmax)
            s = (__half2float(c[j]) + __half2float(p[j + shift])) * SCALE;
        vals[it] = s;
        mx = fmaxf(mx, s);
    }
    __shared__ float redm[8];
    __shared__ float reds[8];
#pragma unroll
    for (int o = 16; o; o >>= 1) mx = fmaxf(mx, __shfl_xor_sync(0xffffffffu, mx, o));
    if ((tid & 31) == 0) redm[tid >> 5] = mx;
    __syncthreads();
    mx = redm[0];
#pragma unroll
    for (int w = 1; w < 8; w++) mx = fmaxf(mx, redm[w]);

    float sum = 0.f;
#pragma unroll
    for (int it = 0; it < 8; it++) {
        float e = __expf(vals[it] - mx);
        vals[it] = e;
        sum += e;
    }
#pragma unroll
    for (int o = 16; o; o >>= 1) sum += __shfl_xor_sync(0xffffffffu, sum, o);
    if ((tid & 31) == 0) reds[tid >> 5] = sum;
    __syncthreads();
    sum = 0.f;
#pragma unroll
    for (int w = 0; w < 8; w++) sum += reds[w];
    float inv = 1.f / sum;

    __half* o = out + rowOff;
#pragma unroll
    for (int it = 0; it < 8; it++) {
        int j = tid + it * 256;
        if (j < WR)
            o[j] = (j <= jmax) ? H(vals[it] * inv) : __half(0.f);
    }
}

// ---------------------------------------------------------------------------
// Context GEMM fp16, cp.async double-buffered. K truncated at i0+1152. (R11)
// ---------------------------------------------------------------------------
__global__ __launch_bounds__(256) void ctx_h(
    const __half* __restrict__ probs, const __half* __restrict__ kv,
    __half* __restrict__ ctx)
{
    int z = blockIdx.y;
    int b = z >> 4, h = z & 15;
    int i0 = blockIdx.x * 128;
    const __half* A0 = probs + (size_t)z * CUR * FULL;
    const __half* B0 = kv + (size_t)b * 2048 + DMODEL + h * HD;

    __shared__ __half sA[2][128 * 40];
    __shared__ __half sB[2][32 * 72];
    __shared__ float  stg[8][256];
    int tid = threadIdx.x, warp = tid >> 5, lid = tid & 31;
    int wm = warp >> 1, wn = warp & 1;

    wmma::fragment<wmma::accumulator, 16, 16, 16, float> acc[2][2];
#pragma unroll
    for (int i = 0; i < 2; i++)
#pragma unroll
        for (int j = 0; j < 2; j++) wmma::fill_fragment(acc[i][j], 0.f);

    int am = tid >> 1, aj = (tid & 1) * 16;
    int bj = tid >> 3, bd = (tid & 7) * 8;
    const __half* Abase = A0 + (size_t)(i0 + am) * FULL + aj;
    const __half* Bbase = B0 + (size_t)bj * (BSZ * 2 * HN * HD) + bd;
    const size_t bstr = (size_t)(BSZ * 2 * HN * HD);

    int kmax = i0 + 1152;  if (kmax > FULL) kmax = FULL;
    int KT = kmax >> 5;

    cp16(&sA[0][am * 40 + aj],     Abase);
    cp16(&sA[0][am * 40 + aj + 8], Abase + 8);
    cp16(&sB[0][bj * 72 + bd],     Bbase);
    CP_COMMIT;

    for (int kt = 0; kt < KT; kt++) {
        if (kt + 1 < KT) {
            int buf = (kt + 1) & 1, k0 = (kt + 1) << 5;
            const __half* ap = Abase + k0;
            const __half* bp = Bbase + (size_t)k0 * bstr;
            cp16(&sA[buf][am * 40 + aj],     ap);
            cp16(&sA[buf][am * 40 + aj + 8], ap + 8);
            cp16(&sB[buf][bj * 72 + bd],     bp);
            CP_COMMIT;
            CP_WAIT1;
        } else {
            CP_WAIT0;
        }
        __syncthreads();
        int cb = kt & 1;
#pragma unroll
        for (int kk = 0; kk < 2; kk++) {
            wmma::fragment<wmma::matrix_a, 16, 16, 16, __half, wmma::row_major> af[2];
            wmma::fragment<wmma::matrix_b, 16, 16, 16, __half, wmma::row_major> bf[2];
#pragma unroll
            for (int i = 0; i < 2; i++)
                wmma::load_matrix_sync(af[i], &sA[cb][(wm * 32 + i * 16) * 40 + kk * 16], 40);
#pragma unroll
            for (int j = 0; j < 2; j++)
                wmma::load_matrix_sync(bf[j], &sB[cb][(kk * 16) * 72 + wn * 32 + j * 16], 72);
#pragma unroll
            for (int i = 0; i < 2; i++)
#pragma unroll
                for (int j = 0; j < 2; j++)
                    wmma::mma_sync(acc[i][j], af[i], bf[j], acc[i][j]);
        }
        __syncthreads();
    }
    int rr = lid >> 1, cc = (lid & 1) * 8;
#pragma unroll
    for (int i = 0; i < 2; i++)
#pragma unroll
        for (int j = 0; j < 2; j++) {
            wmma::store_matrix_sync(&stg[warp][0], acc[i][j], 16, wmma::mem_row_major);
            __syncwarp();
            const float* src = &stg[warp][rr * 16 + cc];
            __half* dst = ctx + (size_t)((i0 + wm * 32 + i * 16 + rr) * BSZ + b) * DMODEL
                              + h * HD + wn * 32 + j * 16 + cc;
#pragma unroll
            for (int t = 0; t < 8; t += 2)
                *reinterpret_cast<__half2*>(dst + t) = __floats2half2_rn(src[t], src[t + 1]);
            __syncwarp();
        }
}

// ---------------------------------------------------------------------------
// Launch
// ---------------------------------------------------------------------------
extern "C" void kernel_launch(void* const* d_in, const int* in_sizes, int n_in,
                              void* d_out, int out_size)
{
    const float* inputs  = (const float*)d_in[0];
    const float* pos_emb = (const float*)d_in[1];
    const float* full_in = (const float*)d_in[2];
    const float* u       = (const float*)d_in[3];
    const float* v       = (const float*)d_in[4];
    const float* W_kv    = (const float*)d_in[6];
    const float* b_kv    = (const float*)d_in[7];
    const float* W_q     = (const float*)d_in[8];
    const float* b_q     = (const float*)d_in[9];
    const float* W_pos   = (const float*)d_in[10];
    const float* W_proj  = (const float*)d_in[12];
    const float* b_proj  = (const float*)d_in[13];
    float* out = (float*)d_out;

    float *q, *beff;
    __half *fullh, *inh, *peh, *Wkvh, *Wqh, *Wposh, *Wprojh;
    __half *kv, *qu, *qv, *r, *ctx, *scores, *pos, *probs;
    cudaGetSymbolAddress((void**)&fullh,  g_full_h);
    cudaGetSymbolAddress((void**)&inh,    g_in_h);
    cudaGetSymbolAddress((void**)&peh,    g_pe_h);
    cudaGetSymbolAddress((void**)&Wkvh,   g_Wkv_h);
    cudaGetSymbolAddress((void**)&Wqh,    g_Wq_h);
    cudaGetSymbolAddress((void**)&Wposh,  g_Wpos_h);
    cudaGetSymbolAddress((void**)&Wprojh, g_Wproj_h);
    cudaGetSymbolAddress((void**)&kv,     g_kv);
    cudaGetSymbolAddress((void**)&q,      g_q);
    cudaGetSymbolAddress((void**)&qu,     g_qu);
    cudaGetSymbolAddress((void**)&qv,     g_qv);
    cudaGetSymbolAddress((void**)&r,      g_r);
    cudaGetSymbolAddress((void**)&ctx,    g_ctx);
    cudaGetSymbolAddress((void**)&scores, g_scores_h);
    cudaGetSymbolAddress((void**)&pos,    g_pos_h);
    cudaGetSymbolAddress((void**)&probs,  g_probs_h);
    cudaGetSymbolAddress((void**)&beff,   g_beff);

    static int attr_set = 0;
    if (!attr_set) {
        cudaFuncSetAttribute(score_h, cudaFuncAttributeMaxDynamicSharedMemorySize,
                             SCORE_SMEM_BYTES);
        attr_set = 1;
    }

    // fp32 -> fp16 converts
    f2h_kernel<<<(8192 * 1024 / 4) / 256, 256>>>(full_in, fullh, 8192 * 1024 / 4);
    f2h_kernel<<<(4096 * 1024 / 4) / 256, 256>>>(inputs, inh, 4096 * 1024 / 4);
    f2h_kernel<<<(2048 * 1024 / 4) / 256, 256>>>(pos_emb, peh, 2048 * 1024 / 4);
    f2h_kernel<<<(1024 * 2048 / 4) / 256, 256>>>(W_kv, Wkvh, 1024 * 2048 / 4);
    f2h_kernel<<<(1024 * 1024 / 4) / 256, 256>>>(W_q, Wqh, 1024 * 1024 / 4);
    f2h_kernel<<<(1024 * 1024 / 4) / 256, 256>>>(W_pos, Wposh, 1024 * 1024 / 4);
    f2h_kernel<<<(1024 * 1024 / 4) / 256, 256>>>(W_proj, Wprojh, 1024 * 1024 / 4);

    // Projections (fp16 in, cp.async pipelined)
    gemm_hh<true ><<<dim3(2048 / 128, 8192 / 128), 256>>>(fullh, Wkvh, kv, 8192, 2048, 1024);
    gemm_hh<false><<<dim3(1024 / 128, 4096 / 128), 256>>>(inh, Wqh, q, 4096, 1024, 1024);
    gemm_hh<true ><<<dim3(1024 / 128, 2048 / 128), 256>>>(peh, Wposh, r, 2048, 1024, 1024);

    quv_kernel<<<4096, 256>>>(q, b_q, u, v, qu, qv);
    beff_kernel<<<DMODEL / 256, 256>>>(b_kv, W_proj, b_proj, beff);

    // Scores (fp16 in/out)
    score_h<<<dim3(FULL / 128, CUR / 128, ZB), 256, SCORE_SMEM_BYTES>>>(qu, kv, scores, 0);
    score_h<<<dim3(FULL / 128, CUR / 128, ZB), 256, SCORE_SMEM_BYTES>>>(qv, r, pos, 1);

    // shift + mask + softmax -> fp16 probs (write-trimmed)
    softmax_kernel<<<dim3(CUR, ZB), 256>>>(scores, pos, probs);

    // ctx = probs @ val (cp.async pipelined)
    ctx_h<<<dim3(CUR / 128, ZB), 256>>>(probs, kv, ctx);

    // out = ctx @ W_proj + b_eff
    gemm_hh<false><<<dim3(1024 / 128, 4096 / 128), 256>>>(ctx, Wprojh, out, 4096, 1024, 1024);
    bias_add_kernel<<<4096, 256>>>(out, beff);

    (void)in_sizes; (void)n_in; (void)out_size;
}

// round 17
// speedup vs baseline: 1.6239x; 1.0983x over previous
#include <cuda_runtime.h>
#include <cuda_fp16.h>
#include <mma.h>
#include <cstdint>

using namespace nvcuda;

// Problem constants
#define CUR    1024
#define FULL   2048
#define BSZ    4
#define DMODEL 1024
#define HN     16
#define HD     64
#define PREV   (FULL - CUR)      // 1024
#define ZB     (BSZ * HN)        // 64 batched heads
#define SCALE  0.125f            // 1/sqrt(64)

// ---------------------------------------------------------------------------
// Scratch
// ---------------------------------------------------------------------------
__device__ __half g_full_h [ (size_t)FULL * BSZ * DMODEL ];
__device__ __half g_in_h   [ (size_t)CUR * BSZ * DMODEL ];
__device__ __half g_pe_h   [ (size_t)FULL * DMODEL ];
__device__ __half g_Wkv_h  [ (size_t)DMODEL * 2 * DMODEL ];
__device__ __half g_Wq_h   [ (size_t)DMODEL * DMODEL ];
__device__ __half g_Wpos_h [ (size_t)DMODEL * DMODEL ];
__device__ __half g_Wproj_h[ (size_t)DMODEL * DMODEL ];

__device__ __half g_kv [ (size_t)FULL * BSZ * 2 * HN * HD ];
__device__ float  g_q  [ (size_t)CUR * BSZ * HN * HD ];
__device__ __half g_qu [ (size_t)CUR * BSZ * HN * HD ];
__device__ __half g_qv [ (size_t)CUR * BSZ * HN * HD ];
__device__ __half g_r  [ (size_t)FULL * HN * HD ];
__device__ __half g_ctx[ (size_t)CUR * BSZ * HN * HD ];
__device__ __half g_scores_h[ (size_t)ZB * CUR * FULL ];
__device__ __half g_pos_h   [ (size_t)ZB * CUR * FULL ];
__device__ __half g_probs_h [ (size_t)ZB * CUR * FULL ];
__device__ float  g_beff[ DMODEL ];

#define H(x) __float2half_rn(x)

// cp.async helpers
__device__ __forceinline__ void cp16(void* smem, const void* gmem) {
    uint32_t s = (uint32_t)__cvta_generic_to_shared(smem);
    asm volatile("cp.async.cg.shared.global [%0], [%1], 16;\n" :: "r"(s), "l"(gmem));
}
#define CP_COMMIT asm volatile("cp.async.commit_group;\n" ::: "memory")
#define CP_WAIT1  asm volatile("cp.async.wait_group 1;\n" ::: "memory")
#define CP_WAIT0  asm volatile("cp.async.wait_group 0;\n" ::: "memory")

// ---------------------------------------------------------------------------
// fp32 -> fp16 convert
// ---------------------------------------------------------------------------
__global__ __launch_bounds__(256) void f2h_kernel(
    const float* __restrict__ src, __half* __restrict__ dst, int n4)
{
    int idx = blockIdx.x * 256 + threadIdx.x;
    if (idx < n4) {
        float4 v = reinterpret_cast<const float4*>(src)[idx];
        reinterpret_cast<__half2*>(dst)[idx * 2 + 0] = __floats2half2_rn(v.x, v.y);
        reinterpret_cast<__half2*>(dst)[idx * 2 + 1] = __floats2half2_rn(v.z, v.w);
    }
}

// ---------------------------------------------------------------------------
// FP16 GEMM, KC=32, cp.async double-buffered (R11/R14 winner): C = A @ B
// 128x128 tile, 8 warps each 64x32.
// ---------------------------------------------------------------------------
template<bool OUT_HALF>
__global__ __launch_bounds__(256) void gemm_hh(
    const __half* __restrict__ A, const __half* __restrict__ B,
    void* __restrict__ Cv, int M, int N, int K)
{
    __shared__ __half sA[2][128 * 40];
    __shared__ __half sB[2][32 * 136];
    __shared__ float  stg[8][256];
    int tid = threadIdx.x, warp = tid >> 5, lid = tid & 31;
    int wm = warp >> 2, wn = warp & 3;
    int m0 = blockIdx.y * 128, n0 = blockIdx.x * 128;

    wmma::fragment<wmma::accumulator, 16, 16, 16, float> acc[4][2];
#pragma unroll
    for (int i = 0; i < 4; i++)
#pragma unroll
        for (int j = 0; j < 2; j++) wmma::fill_fragment(acc[i][j], 0.f);

    int am = tid >> 1,  ak = (tid & 1) * 16;
    int bk = tid >> 3,  bn = (tid & 7) * 16;
    const __half* Abase = A + (size_t)(m0 + am) * K + ak;
    const __half* Bbase = B + (size_t)bk * N + n0 + bn;

    int KT = K >> 5;
    cp16(&sA[0][am * 40 + ak],     Abase);
    cp16(&sA[0][am * 40 + ak + 8], Abase + 8);
    cp16(&sB[0][bk * 136 + bn],     Bbase);
    cp16(&sB[0][bk * 136 + bn + 8], Bbase + 8);
    CP_COMMIT;

    for (int kt = 0; kt < KT; kt++) {
        if (kt + 1 < KT) {
            int buf = (kt + 1) & 1, k0 = (kt + 1) << 5;
            const __half* ap = Abase + k0;
            const __half* bp = Bbase + (size_t)k0 * N;
            cp16(&sA[buf][am * 40 + ak],     ap);
            cp16(&sA[buf][am * 40 + ak + 8], ap + 8);
            cp16(&sB[buf][bk * 136 + bn],     bp);
            cp16(&sB[buf][bk * 136 + bn + 8], bp + 8);
            CP_COMMIT;
            CP_WAIT1;
        } else {
            CP_WAIT0;
        }
        __syncthreads();
        int cb = kt & 1;
#pragma unroll
        for (int kk = 0; kk < 2; kk++) {
            wmma::fragment<wmma::matrix_a, 16, 16, 16, __half, wmma::row_major> af[4];
            wmma::fragment<wmma::matrix_b, 16, 16, 16, __half, wmma::row_major> bf[2];
#pragma unroll
            for (int i = 0; i < 4; i++)
                wmma::load_matrix_sync(af[i], &sA[cb][(wm * 64 + i * 16) * 40 + kk * 16], 40);
#pragma unroll
            for (int j = 0; j < 2; j++)
                wmma::load_matrix_sync(bf[j], &sB[cb][(kk * 16) * 136 + wn * 32 + j * 16], 136);
#pragma unroll
            for (int i = 0; i < 4; i++)
#pragma unroll
                for (int j = 0; j < 2; j++)
                    wmma::mma_sync(acc[i][j], af[i], bf[j], acc[i][j]);
        }
        __syncthreads();
    }

    if (OUT_HALF) {
        __half* C = reinterpret_cast<__half*>(Cv);
        int rr = lid >> 1, cc = (lid & 1) * 8;
#pragma unroll
        for (int i = 0; i < 4; i++)
#pragma unroll
            for (int j = 0; j < 2; j++) {
                wmma::store_matrix_sync(&stg[warp][0], acc[i][j], 16, wmma::mem_row_major);
                __syncwarp();
                const float* src = &stg[warp][rr * 16 + cc];
                __half* dst = C + (size_t)(m0 + wm * 64 + i * 16 + rr) * N
                                + n0 + wn * 32 + j * 16 + cc;
#pragma unroll
                for (int t = 0; t < 8; t += 2)
                    *reinterpret_cast<__half2*>(dst + t) = __floats2half2_rn(src[t], src[t + 1]);
                __syncwarp();
            }
    } else {
        float* C = reinterpret_cast<float*>(Cv);
#pragma unroll
        for (int i = 0; i < 4; i++)
#pragma unroll
            for (int j = 0; j < 2; j++)
                wmma::store_matrix_sync(
                    C + (size_t)(m0 + wm * 64 + i * 16) * N + n0 + wn * 32 + j * 16,
                    acc[i][j], N, wmma::mem_row_major);
    }
}

// ---------------------------------------------------------------------------
// Final GEMM with fused bias: C[M,N] = A @ B + beff[n]  (fp32 out)
// Same mainloop as gemm_hh; bias added in fp32 epilogue via staging.
// ---------------------------------------------------------------------------
__global__ __launch_bounds__(256) void gemm_outb(
    const __half* __restrict__ A, const __half* __restrict__ B,
    const float* __restrict__ beff, float* __restrict__ C, int M, int N, int K)
{
    __shared__ __half sA[2][128 * 40];
    __shared__ __half sB[2][32 * 136];
    __shared__ float  stg[8][256];
    int tid = threadIdx.x, warp = tid >> 5, lid = tid & 31;
    int wm = warp >> 2, wn = warp & 3;
    int m0 = blockIdx.y * 128, n0 = blockIdx.x * 128;

    wmma::fragment<wmma::accumulator, 16, 16, 16, float> acc[4][2];
#pragma unroll
    for (int i = 0; i < 4; i++)
#pragma unroll
        for (int j = 0; j < 2; j++) wmma::fill_fragment(acc[i][j], 0.f);

    int am = tid >> 1,  ak = (tid & 1) * 16;
    int bk = tid >> 3,  bn = (tid & 7) * 16;
    const __half* Abase = A + (size_t)(m0 + am) * K + ak;
    const __half* Bbase = B + (size_t)bk * N + n0 + bn;

    int KT = K >> 5;
    cp16(&sA[0][am * 40 + ak],     Abase);
    cp16(&sA[0][am * 40 + ak + 8], Abase + 8);
    cp16(&sB[0][bk * 136 + bn],     Bbase);
    cp16(&sB[0][bk * 136 + bn + 8], Bbase + 8);
    CP_COMMIT;

    for (int kt = 0; kt < KT; kt++) {
        if (kt + 1 < KT) {
            int buf = (kt + 1) & 1, k0 = (kt + 1) << 5;
            const __half* ap = Abase + k0;
            const __half* bp = Bbase + (size_t)k0 * N;
            cp16(&sA[buf][am * 40 + ak],     ap);
            cp16(&sA[buf][am * 40 + ak + 8], ap + 8);
            cp16(&sB[buf][bk * 136 + bn],     bp);
            cp16(&sB[buf][bk * 136 + bn + 8], bp + 8);
            CP_COMMIT;
            CP_WAIT1;
        } else {
            CP_WAIT0;
        }
        __syncthreads();
        int cb = kt & 1;
#pragma unroll
        for (int kk = 0; kk < 2; kk++) {
            wmma::fragment<wmma::matrix_a, 16, 16, 16, __half, wmma::row_major> af[4];
            wmma::fragment<wmma::matrix_b, 16, 16, 16, __half, wmma::row_major> bf[2];
#pragma unroll
            for (int i = 0; i < 4; i++)
                wmma::load_matrix_sync(af[i], &sA[cb][(wm * 64 + i * 16) * 40 + kk * 16], 40);
#pragma unroll
            for (int j = 0; j < 2; j++)
                wmma::load_matrix_sync(bf[j], &sB[cb][(kk * 16) * 136 + wn * 32 + j * 16], 136);
#pragma unroll
            for (int i = 0; i < 4; i++)
#pragma unroll
                for (int j = 0; j < 2; j++)
                    wmma::mma_sync(acc[i][j], af[i], bf[j], acc[i][j]);
        }
        __syncthreads();
    }

    int rr = lid >> 1, cc = (lid & 1) * 8;
#pragma unroll
    for (int i = 0; i < 4; i++)
#pragma unroll
        for (int j = 0; j < 2; j++) {
            wmma::store_matrix_sync(&stg[warp][0], acc[i][j], 16, wmma::mem_row_major);
            __syncwarp();
            const float* src = &stg[warp][rr * 16 + cc];
            int n = n0 + wn * 32 + j * 16 + cc;
            float* dst = C + (size_t)(m0 + wm * 64 + i * 16 + rr) * N + n;
            float4 o0, o1;
            o0.x = src[0] + beff[n + 0]; o0.y = src[1] + beff[n + 1];
            o0.z = src[2] + beff[n + 2]; o0.w = src[3] + beff[n + 3];
            o1.x = src[4] + beff[n + 4]; o1.y = src[5] + beff[n + 5];
            o1.z = src[6] + beff[n + 6]; o1.w = src[7] + beff[n + 7];
            *reinterpret_cast<float4*>(dst)     = o0;
            *reinterpret_cast<float4*>(dst + 4) = o1;
            __syncwarp();
        }
}

// ---------------------------------------------------------------------------
// qu/qv
// ---------------------------------------------------------------------------
__global__ __launch_bounds__(256) void quv_kernel(
    const float* __restrict__ q, const float* __restrict__ b_q,
    const float* __restrict__ u, const float* __restrict__ v,
    __half* __restrict__ qu, __half* __restrict__ qv)
{
    int idx = blockIdx.x * 256 + threadIdx.x;
    int n4 = idx & 255;
    float4 qq = reinterpret_cast<const float4*>(q)[idx];
    float4 bb = reinterpret_cast<const float4*>(b_q)[n4];
    float4 uu = reinterpret_cast<const float4*>(u)[n4];
    float4 vv = reinterpret_cast<const float4*>(v)[n4];
    reinterpret_cast<__half2*>(qu)[idx * 2 + 0] = __floats2half2_rn(qq.x + bb.x + uu.x, qq.y + bb.y + uu.y);
    reinterpret_cast<__half2*>(qu)[idx * 2 + 1] = __floats2half2_rn(qq.z + bb.z + uu.z, qq.w + bb.w + uu.w);
    reinterpret_cast<__half2*>(qv)[idx * 2 + 0] = __floats2half2_rn(qq.x + bb.x + vv.x, qq.y + bb.y + vv.y);
    reinterpret_cast<__half2*>(qv)[idx * 2 + 1] = __floats2half2_rn(qq.z + bb.z + vv.z, qq.w + bb.w + vv.w);
}

// beff, parallel version: grid 32 blocks; block = 8 m-chunks x 32 n
__global__ __launch_bounds__(256) void beff_kernel2(
    const float* __restrict__ b_kv, const float* __restrict__ W_proj,
    const float* __restrict__ b_proj, float* __restrict__ beff)
{
    __shared__ float red[8][32];
    int nc = threadIdx.x & 31, mr = threadIdx.x >> 5;
    int n = blockIdx.x * 32 + nc;
    float acc = 0.f;
    int mbeg = mr * 128;
    for (int m = mbeg; m < mbeg + 128; m++)
        acc += b_kv[DMODEL + m] * W_proj[(size_t)m * DMODEL + n];
    red[mr][nc] = acc;
    __syncthreads();
    if (mr == 0) {
        float s = b_proj[n];
#pragma unroll
        for (int w = 0; w < 8; w++) s += red[w][nc];
        beff[n] = s;
    }
}

// ---------------------------------------------------------------------------
// Score GEMM (fp16 in/out), single-shot K=64.  (R14)
// ---------------------------------------------------------------------------
#define SCORE_SMEM_BYTES (128 * 132 * 4)
__global__ __launch_bounds__(256) void score_h(
    const __half* __restrict__ QU, const __half* __restrict__ SRC,
    __half* __restrict__ OUT, int isPos)
{
    int i0 = blockIdx.y * 128, j0 = blockIdx.x * 128;
    if (!isPos && j0 >= i0 + 1152) return;
    if (isPos && (i0 + j0 + 254) < 1023) return;
    int z = blockIdx.z;
    int b = z >> 4, h = z & 15;
    const __half* A0 = QU + b * DMODEL + h * HD;
    const __half* B0 = isPos ? (SRC + h * HD) : (SRC + b * 2048 + h * HD);
    size_t ldB = isPos ? (size_t)(HN * HD) : (size_t)(BSZ * 2 * HN * HD);

    extern __shared__ char dynsm[];
    __half* sA = reinterpret_cast<__half*>(dynsm);           // 128 x 72
    __half* sB = sA + 128 * 72;
    float*  stage = reinterpret_cast<float*>(dynsm);

    int tid = threadIdx.x, warp = tid >> 5;
    int wm = warp >> 2, wn = warp & 3;

    wmma::fragment<wmma::accumulator, 16, 16, 16, float> acc[4][2];
#pragma unroll
    for (int i = 0; i < 4; i++)
#pragma unroll
        for (int j = 0; j < 2; j++) wmma::fill_fragment(acc[i][j], 0.f);

    int rm = tid >> 1, rk = (tid & 1) * 32;
    {
        const __half* ap = A0 + (size_t)(i0 + rm) * (BSZ * DMODEL) + rk;
        __half* sa = sA + rm * 72 + rk;
#pragma unroll
        for (int s = 0; s < 4; s++)
            *reinterpret_cast<uint4*>(sa + 8 * s) = *reinterpret_cast<const uint4*>(ap + 8 * s);
        const __half* bp = B0 + (size_t)(j0 + rm) * ldB + rk;
        __half* sb = sB + rm * 72 + rk;
#pragma unroll
        for (int s = 0; s < 4; s++)
            *reinterpret_cast<uint4*>(sb + 8 * s) = *reinterpret_cast<const uint4*>(bp + 8 * s);
    }
    __syncthreads();
#pragma unroll
    for (int kk = 0; kk < 4; kk++) {
        wmma::fragment<wmma::matrix_a, 16, 16, 16, __half, wmma::row_major> af[4];
        wmma::fragment<wmma::matrix_b, 16, 16, 16, __half, wmma::col_major> bf[2];
#pragma unroll
        for (int i = 0; i < 4; i++)
            wmma::load_matrix_sync(af[i], &sA[(wm * 64 + i * 16) * 72 + kk * 16], 72);
#pragma unroll
        for (int j = 0; j < 2; j++)
            wmma::load_matrix_sync(bf[j], &sB[(wn * 32 + j * 16) * 72 + kk * 16], 72);
#pragma unroll
        for (int i = 0; i < 4; i++)
#pragma unroll
            for (int j = 0; j < 2; j++)
                wmma::mma_sync(acc[i][j], af[i], bf[j], acc[i][j]);
    }
    __syncthreads();

#pragma unroll
    for (int i = 0; i < 4; i++)
#pragma unroll
        for (int j = 0; j < 2; j++)
            wmma::store_matrix_sync(&stage[(wm * 64 + i * 16) * 132 + wn * 32 + j * 16],
                                    acc[i][j], 132, wmma::mem_row_major);
    __syncthreads();

    __half* C0 = OUT + (size_t)z * CUR * FULL;
    int row = tid >> 1, cb = (tid & 1) * 64;
    __half* dst = C0 + (size_t)(i0 + row) * FULL + j0 + cb;
    const float* src = stage + row * 132 + cb;
#pragma unroll
    for (int t = 0; t < 64; t += 2)
        *reinterpret_cast<__half2*>(dst + t) = __floats2half2_rn(src[t], src[t + 1]);
}

// ---------------------------------------------------------------------------
// Fused rel_shift gather + mask + softmax (write-trimmed).  (R14)
// ---------------------------------------------------------------------------
__global__ __launch_bounds__(256) void softmax_kernel(
    const __half* __restrict__ cont, const __half* __restrict__ pos,
    __half* __restrict__ out)
{
    int i = blockIdx.x;
    int z = blockIdx.y;
    int tid = threadIdx.x;
    size_t rowOff = ((size_t)z * CUR + i) * FULL;
    const __half* c = cont + rowOff;
    const __half* p = pos + rowOff;
    int jmax  = i + PREV;
    int shift = CUR - 1 - i;
    int WR = (i & ~127) + 1152;  if (WR > FULL) WR = FULL;

    float vals[8];
    float mx = -1e30f;
#pragma unroll
    for (int it = 0; it < 8; it++) {
        int j = tid + it * 256;
        float s = -1e30f;
        if (j <= jmax)
            s = (__half2float(c[j]) + __half2float(p[j + shift])) * SCALE;
        vals[it] = s;
        mx = fmaxf(mx, s);
    }
    __shared__ float redm[8];
    __shared__ float reds[8];
#pragma unroll
    for (int o = 16; o; o >>= 1) mx = fmaxf(mx, __shfl_xor_sync(0xffffffffu, mx, o));
    if ((tid & 31) == 0) redm[tid >> 5] = mx;
    __syncthreads();
    mx = redm[0];
#pragma unroll
    for (int w = 1; w < 8; w++) mx = fmaxf(mx, redm[w]);

    float sum = 0.f;
#pragma unroll
    for (int it = 0; it < 8; it++) {
        float e = __expf(vals[it] - mx);
        vals[it] = e;
        sum += e;
    }
#pragma unroll
    for (int o = 16; o; o >>= 1) sum += __shfl_xor_sync(0xffffffffu, sum, o);
    if ((tid & 31) == 0) reds[tid >> 5] = sum;
    __syncthreads();
    sum = 0.f;
#pragma unroll
    for (int w = 0; w < 8; w++) sum += reds[w];
    float inv = 1.f / sum;

    __half* o = out + rowOff;
#pragma unroll
    for (int it = 0; it < 8; it++) {
        int j = tid + it * 256;
        if (j < WR)
            o[j] = (j <= jmax) ? H(vals[it] * inv) : __half(0.f);
    }
}

// ---------------------------------------------------------------------------
// Context GEMM fp16, cp.async double-buffered. K truncated at i0+1152. (R14)
// ---------------------------------------------------------------------------
__global__ __launch_bounds__(256) void ctx_h(
    const __half* __restrict__ probs, const __half* __restrict__ kv,
    __half* __restrict__ ctx)
{
    int z = blockIdx.y;
    int b = z >> 4, h = z & 15;
    int i0 = blockIdx.x * 128;
    const __half* A0 = probs + (size_t)z * CUR * FULL;
    const __half* B0 = kv + (size_t)b * 2048 + DMODEL + h * HD;

    __shared__ __half sA[2][128 * 40];
    __shared__ __half sB[2][32 * 72];
    __shared__ float  stg[8][256];
    int tid = threadIdx.x, warp = tid >> 5, lid = tid & 31;
    int wm = warp >> 1, wn = warp & 1;

    wmma::fragment<wmma::accumulator, 16, 16, 16, float> acc[2][2];
#pragma unroll
    for (int i = 0; i < 2; i++)
#pragma unroll
        for (int j = 0; j < 2; j++) wmma::fill_fragment(acc[i][j], 0.f);

    int am = tid >> 1, aj = (tid & 1) * 16;
    int bj = tid >> 3, bd = (tid & 7) * 8;
    const __half* Abase = A0 + (size_t)(i0 + am) * FULL + aj;
    const __half* Bbase = B0 + (size_t)bj * (BSZ * 2 * HN * HD) + bd;
    const size_t bstr = (size_t)(BSZ * 2 * HN * HD);

    int kmax = i0 + 1152;  if (kmax > FULL) kmax = FULL;
    int KT = kmax >> 5;

    cp16(&sA[0][am * 40 + aj],     Abase);
    cp16(&sA[0][am * 40 + aj + 8], Abase + 8);
    cp16(&sB[0][bj * 72 + bd],     Bbase);
    CP_COMMIT;

    for (int kt = 0; kt < KT; kt++) {
        if (kt + 1 < KT) {
            int buf = (kt + 1) & 1, k0 = (kt + 1) << 5;
            const __half* ap = Abase + k0;
            const __half* bp = Bbase + (size_t)k0 * bstr;
            cp16(&sA[buf][am * 40 + aj],     ap);
            cp16(&sA[buf][am * 40 + aj + 8], ap + 8);
            cp16(&sB[buf][bj * 72 + bd],     bp);
            CP_COMMIT;
            CP_WAIT1;
        } else {
            CP_WAIT0;
        }
        __syncthreads();
        int cb = kt & 1;
#pragma unroll
        for (int kk = 0; kk < 2; kk++) {
            wmma::fragment<wmma::matrix_a, 16, 16, 16, __half, wmma::row_major> af[2];
            wmma::fragment<wmma::matrix_b, 16, 16, 16, __half, wmma::row_major> bf[2];
#pragma unroll
            for (int i = 0; i < 2; i++)
                wmma::load_matrix_sync(af[i], &sA[cb][(wm * 32 + i * 16) * 40 + kk * 16], 40);
#pragma unroll
            for (int j = 0; j < 2; j++)
                wmma::load_matrix_sync(bf[j], &sB[cb][(kk * 16) * 72 + wn * 32 + j * 16], 72);
#pragma unroll
            for (int i = 0; i < 2; i++)
#pragma unroll
                for (int j = 0; j < 2; j++)
                    wmma::mma_sync(acc[i][j], af[i], bf[j], acc[i][j]);
        }
        __syncthreads();
    }
    int rr = lid >> 1, cc = (lid & 1) * 8;
#pragma unroll
    for (int i = 0; i < 2; i++)
#pragma unroll
        for (int j = 0; j < 2; j++) {
            wmma::store_matrix_sync(&stg[warp][0], acc[i][j], 16, wmma::mem_row_major);
            __syncwarp();
            const float* src = &stg[warp][rr * 16 + cc];
            __half* dst = ctx + (size_t)((i0 + wm * 32 + i * 16 + rr) * BSZ + b) * DMODEL
                              + h * HD + wn * 32 + j * 16 + cc;
#pragma unroll
            for (int t = 0; t < 8; t += 2)
                *reinterpret_cast<__half2*>(dst + t) = __floats2half2_rn(src[t], src[t + 1]);
            __syncwarp();
        }
}

// ---------------------------------------------------------------------------
// Launch: fork/join on 3 streams for overlap (capture-legal pattern).
// ---------------------------------------------------------------------------
extern "C" void kernel_launch(void* const* d_in, const int* in_sizes, int n_in,
                              void* d_out, int out_size)
{
    const float* inputs  = (const float*)d_in[0];
    const float* pos_emb = (const float*)d_in[1];
    const float* full_in = (const float*)d_in[2];
    const float* u       = (const float*)d_in[3];
    const float* v       = (const float*)d_in[4];
    const float* W_kv    = (const float*)d_in[6];
    const float* b_kv    = (const float*)d_in[7];
    const float* W_q     = (const float*)d_in[8];
    const float* b_q     = (const float*)d_in[9];
    const float* W_pos   = (const float*)d_in[10];
    const float* W_proj  = (const float*)d_in[12];
    const float* b_proj  = (const float*)d_in[13];
    float* out = (float*)d_out;

    float *q, *beff;
    __half *fullh, *inh, *peh, *Wkvh, *Wqh, *Wposh, *Wprojh;
    __half *kv, *qu, *qv, *r, *ctx, *scores, *pos, *probs;
    cudaGetSymbolAddress((void**)&fullh,  g_full_h);
    cudaGetSymbolAddress((void**)&inh,    g_in_h);
    cudaGetSymbolAddress((void**)&peh,    g_pe_h);
    cudaGetSymbolAddress((void**)&Wkvh,   g_Wkv_h);
    cudaGetSymbolAddress((void**)&Wqh,    g_Wq_h);
    cudaGetSymbolAddress((void**)&Wposh,  g_Wpos_h);
    cudaGetSymbolAddress((void**)&Wprojh, g_Wproj_h);
    cudaGetSymbolAddress((void**)&kv,     g_kv);
    cudaGetSymbolAddress((void**)&q,      g_q);
    cudaGetSymbolAddress((void**)&qu,     g_qu);
    cudaGetSymbolAddress((void**)&qv,     g_qv);
    cudaGetSymbolAddress((void**)&r,      g_r);
    cudaGetSymbolAddress((void**)&ctx,    g_ctx);
    cudaGetSymbolAddress((void**)&scores, g_scores_h);
    cudaGetSymbolAddress((void**)&pos,    g_pos_h);
    cudaGetSymbolAddress((void**)&probs,  g_probs_h);
    cudaGetSymbolAddress((void**)&beff,   g_beff);

    static cudaStream_t s1 = nullptr, s2 = nullptr;
    static cudaEvent_t evR = nullptr, ev1 = nullptr, ev2 = nullptr;
    static int attr_set = 0;
    if (!attr_set) {
        cudaFuncSetAttribute(score_h, cudaFuncAttributeMaxDynamicSharedMemorySize,
                             SCORE_SMEM_BYTES);
        cudaStreamCreateWithFlags(&s1, cudaStreamNonBlocking);
        cudaStreamCreateWithFlags(&s2, cudaStreamNonBlocking);
        cudaEventCreateWithFlags(&evR, cudaEventDisableTiming);
        cudaEventCreateWithFlags(&ev1, cudaEventDisableTiming);
        cudaEventCreateWithFlags(&ev2, cudaEventDisableTiming);
        attr_set = 1;
    }

    // ---- fork ----
    cudaEventRecord(evR, 0);
    cudaStreamWaitEvent(s1, evR, 0);
    cudaStreamWaitEvent(s2, evR, 0);

    // s1: q chain -> qu/qv
    f2h_kernel<<<(4096 * 1024 / 4) / 256, 256, 0, s1>>>(inputs, inh, 4096 * 1024 / 4);
    f2h_kernel<<<(1024 * 1024 / 4) / 256, 256, 0, s1>>>(W_q, Wqh, 1024 * 1024 / 4);
    gemm_hh<false><<<dim3(1024 / 128, 4096 / 128), 256, 0, s1>>>(inh, Wqh, q, 4096, 1024, 1024);
    quv_kernel<<<4096, 256, 0, s1>>>(q, b_q, u, v, qu, qv);
    cudaEventRecord(ev1, s1);

    // s2: r chain + W_proj/beff, then pos scores (needs qv via ev1)
    f2h_kernel<<<(2048 * 1024 / 4) / 256, 256, 0, s2>>>(pos_emb, peh, 2048 * 1024 / 4);
    f2h_kernel<<<(1024 * 1024 / 4) / 256, 256, 0, s2>>>(W_pos, Wposh, 1024 * 1024 / 4);
    gemm_hh<true ><<<dim3(1024 / 128, 2048 / 128), 256, 0, s2>>>(peh, Wposh, r, 2048, 1024, 1024);
    f2h_kernel<<<(1024 * 1024 / 4) / 256, 256, 0, s2>>>(W_proj, Wprojh, 1024 * 1024 / 4);
    beff_kernel2<<<DMODEL / 32, 256, 0, s2>>>(b_kv, W_proj, b_proj, beff);
    cudaStreamWaitEvent(s2, ev1, 0);
    score_h<<<dim3(FULL / 128, CUR / 128, ZB), 256, SCORE_SMEM_BYTES, s2>>>(qv, r, pos, 1);
    cudaEventRecord(ev2, s2);

    // s0 (default): kv chain, content scores, then join and finish
    f2h_kernel<<<(8192 * 1024 / 4) / 256, 256>>>(full_in, fullh, 8192 * 1024 / 4);
    f2h_kernel<<<(1024 * 2048 / 4) / 256, 256>>>(W_kv, Wkvh, 1024 * 2048 / 4);
    gemm_hh<true ><<<dim3(2048 / 128, 8192 / 128), 256>>>(fullh, Wkvh, kv, 8192, 2048, 1024);
    cudaStreamWaitEvent(0, ev1, 0);
    score_h<<<dim3(FULL / 128, CUR / 128, ZB), 256, SCORE_SMEM_BYTES>>>(qu, kv, scores, 0);
    cudaStreamWaitEvent(0, ev2, 0);
    softmax_kernel<<<dim3(CUR, ZB), 256>>>(scores, pos, probs);
    ctx_h<<<dim3(CUR / 128, ZB), 256>>>(probs, kv, ctx);
    gemm_outb<<<dim3(1024 / 128, 4096 / 128), 256>>>(ctx, Wprojh, beff, out, 4096, 1024, 1024);

    (void)in_sizes; (void)n_in; (void)out_size;
}